// round 16
// baseline (speedup 1.0000x reference)
#include <cuda_runtime.h>
#include <cuda_bf16.h>

// MulticlassDice fused: nibble-packed histograms, hierarchical completion tail.
// R13 skeleton (plain __syncthreads, early warp exit AFTER barrier) + per-sample
// completion counters. Inputs proven int32 (R5 traffic = 16.8 MB).
// dice[n][c] = (2*inter + 1e-5) / (cnt_in + cnt_tg + 1e-5)
// Output: [total, dice[0..7]] (verified across R3..R13).

#define NCLS 8
#define PIX (512 * 512)
#define MAXN 8
#define GXB 74            // blocks per sample: 74*8 = 592 = 4/SM on 148 SMs
#define BT 256
#define NWARP (BT / 32)   // 8
#define NSLOT (3 * NCLS)  // 24
#define W32 (PIX / 4)     // 65536 int4 words per sample
#define CH32 ((W32 + GXB - 1) / GXB)  // 886

__device__ int g_cnt[MAXN][NSLOT];       // zero-init; final winner re-zeros
__device__ float g_dice[MAXN][NCLS];     // per-sample dice (overwritten each launch)
__device__ unsigned int g_done_s[MAXN];  // per-sample arrival counters
__device__ unsigned int g_done2;         // sample-winner counter

__device__ __forceinline__ void acc_px(int a, int b, unsigned& hin, unsigned& htg,
                                       unsigned& hxx) {
    unsigned sa = 1u << (4 * a);
    unsigned sb = 1u << (4 * b);
    hin += sa;
    htg += sb;
    if (a == b) hxx += sa;
}

__device__ __forceinline__ void acc4(const int4& va, const int4& vb, unsigned& hin,
                                     unsigned& htg, unsigned& hxx) {
    acc_px(va.x, vb.x, hin, htg, hxx);
    acc_px(va.y, vb.y, hin, htg, hxx);
    acc_px(va.z, vb.z, hin, htg, hxx);
    acc_px(va.w, vb.w, hin, htg, hxx);
}

// nibbles (cap 16) -> byte-packed (cap 256)
__device__ __forceinline__ void drain1(unsigned& h, unsigned& be, unsigned& bo) {
    be += h & 0x0F0F0F0Fu;
    bo += (h >> 4) & 0x0F0F0F0Fu;
    h = 0u;
}

__device__ __forceinline__ unsigned atom_inc_acqrel(unsigned int* p) {
    unsigned prev;
    asm volatile("atom.add.acq_rel.gpu.u32 %0, [%1], %2;"
                 : "=r"(prev) : "l"(p), "r"(1u) : "memory");
    return prev;
}

__global__ __launch_bounds__(BT, 4) void k_dice_fused(const int* __restrict__ inB,
                                                      const int* __restrict__ tgB,
                                                      const float* __restrict__ w,
                                                      float* __restrict__ out,
                                                      int out_size, int N) {
    const int n = blockIdx.y;
    const int tid = threadIdx.x;
    const int lid = tid & 31;
    const int wid = tid >> 5;  // 0..7
    const unsigned FULL = 0xffffffffu;

    // ---- mainloop: loads first, all front-batched (8 LDG.128 per thread) ----
    const int4* a = (const int4*)inB + (size_t)n * W32;
    const int4* b = (const int4*)tgB + (size_t)n * W32;
    const int start = blockIdx.x * CH32;
    const int end = min(start + CH32, W32);
    const int i0 = start + tid, i1 = i0 + BT, i2 = i0 + 2 * BT, i3 = i0 + 3 * BT;
    const bool v0 = i0 < end, v1 = i1 < end, v2 = i2 < end, v3 = i3 < end;
    int4 a0, a1, a2, a3, b0, b1, b2, b3;
    if (v0) { a0 = a[i0]; b0 = b[i0]; }
    if (v1) { a1 = a[i1]; b1 = b[i1]; }
    if (v2) { a2 = a[i2]; b2 = b[i2]; }
    if (v3) { a3 = a[i3]; b3 = b[i3]; }

    unsigned hin = 0, htg = 0, hxx = 0;
    unsigned be_in = 0, bo_in = 0, be_tg = 0, bo_tg = 0, be_xx = 0, bo_xx = 0;

    // 16 px/thread max; drain at 8 px to respect nibble cap 15
    if (v0) acc4(a0, b0, hin, htg, hxx);
    if (v1) acc4(a1, b1, hin, htg, hxx);
    drain1(hin, be_in, bo_in);
    drain1(htg, be_tg, bo_tg);
    drain1(hxx, be_xx, bo_xx);
    if (v2) acc4(a2, b2, hin, htg, hxx);
    if (v3) acc4(a3, b3, hin, htg, hxx);
    drain1(hin, be_in, bo_in);
    drain1(htg, be_tg, bo_tg);
    drain1(hxx, be_xx, bo_xx);

    // ---- pack byte counters into 16-bit pairs, 12 REDUX per warp ----
    // per type: r0=(c0,c4), r1=(c2,c6), r2=(c1,c5), r3=(c3,c7)
    const unsigned M = 0x00FF00FFu;
    unsigned r[12];
    r[0] = be_in & M;  r[1] = (be_in >> 8) & M;
    r[2] = bo_in & M;  r[3] = (bo_in >> 8) & M;
    r[4] = be_tg & M;  r[5] = (be_tg >> 8) & M;
    r[6] = bo_tg & M;  r[7] = (bo_tg >> 8) & M;
    r[8] = be_xx & M;  r[9] = (be_xx >> 8) & M;
    r[10] = bo_xx & M; r[11] = (bo_xx >> 8) & M;
#pragma unroll
    for (int j = 0; j < 12; j++) r[j] = __reduce_add_sync(FULL, r[j]);

    __shared__ unsigned s_ph[NWARP][12];
    if (lid == 0) {
#pragma unroll
        for (int j = 0; j < 12; j++) s_ph[wid][j] = r[j];
    }
    __syncthreads();
    if (wid != 0) return;  // warps 1..7 done; warp 0 owns publish + epilogue

    // ---- warp 0: gather 24 slots across 8 warps, publish to g_cnt ----
    if (lid < NSLOT) {
        int t = lid / NCLS, c = lid % NCLS;
        int j = t * 4 + (c & 1) * 2 + ((c >> 1) & 1);
        int h = (c >> 2) * 16;
        int acc = 0;
#pragma unroll
        for (int ww = 0; ww < NWARP; ww++) acc += (int)((s_ph[ww][j] >> h) & 0xFFFFu);
        atomicAdd(&g_cnt[n][lid], acc);
    }
    __syncwarp(FULL);

    // ---- per-sample completion (74 arrivals on 8 parallel addresses) ----
    unsigned prev = 0;
    if (lid == 0) prev = atom_inc_acqrel(&g_done_s[n]);
    prev = __shfl_sync(FULL, prev, 0);
    if (prev != (unsigned)(GXB - 1)) return;

    // sample winner: lanes 0..7 compute dice[n][c]
    if (lid < NCLS) {
        float cnt_in = (float)g_cnt[n][0 * NCLS + lid];
        float cnt_tg = (float)g_cnt[n][1 * NCLS + lid];
        float inter = (float)g_cnt[n][2 * NCLS + lid];
        g_dice[n][lid] = (2.0f * inter + 1e-5f) / (cnt_in + cnt_tg + 1e-5f);
    }
    __syncwarp(FULL);

    // ---- global completion (only N arrivals) ----
    unsigned prev2 = 0;
    if (lid == 0) prev2 = atom_inc_acqrel(&g_done2);
    prev2 = __shfl_sync(FULL, prev2, 0);
    if (prev2 != (unsigned)(N - 1)) return;

    // ---- final winner: shuffle epilogue over 64 dice floats ----
    float wc = (lid < NCLS) ? __ldg(&w[lid]) : 0.0f;  // issue early

    const int c = lid & 7;
    const int h0 = lid >> 3;  // 0..3
    float m = 0.0f;
    if (h0 < N) m += g_dice[h0][c];
    if (h0 + 4 < N) m += g_dice[h0 + 4][c];
    m += __shfl_xor_sync(FULL, m, 8);
    m += __shfl_xor_sync(FULL, m, 16);
    const float mean = m / (float)N;  // lanes 0..7: mean dice of class lid

    float t = (lid < NCLS) ? wc * mean : 0.0f;
    t += __shfl_xor_sync(FULL, t, 1);
    t += __shfl_xor_sync(FULL, t, 2);
    t += __shfl_xor_sync(FULL, t, 4);
    const float total = __shfl_sync(FULL, t, 0);

    if (out_size >= NCLS + 1) {
        if (lid == 0) out[0] = total;
        if (lid < NCLS) out[1 + lid] = mean;  // lane's c == lid for lid<8
        for (int i = NCLS + 1 + lid; i < out_size; i += 32) out[i] = 0.0f;
    } else if (out_size == NCLS) {
        if (lid < NCLS) out[lid] = mean;
    } else {
        if (lid == 0 && out_size > 0) out[0] = total;
        for (int i = 1 + lid; i < out_size; i += 32) out[i] = (i - 1 < NCLS) ? mean : 0.0f;
    }

    // ---- reset state for next graph replay (kernel boundary publishes) ----
    for (int i = lid; i < MAXN * NSLOT; i += 32) ((int*)g_cnt)[i] = 0;
    if (lid < MAXN) g_done_s[lid] = 0u;
    if (lid == 0) g_done2 = 0u;
}

extern "C" void kernel_launch(void* const* d_in, const int* in_sizes, int n_in,
                              void* d_out, int out_size) {
    const int* inB = (const int*)d_in[0];
    const int* tgB = (const int*)d_in[1];
    const float* w = (const float*)d_in[2];
    float* out = (float*)d_out;

    int N = in_sizes[0] / PIX;
    if (N < 1) N = 1;
    if (N > MAXN) N = MAXN;

    dim3 grid(GXB, N);
    k_dice_fused<<<grid, BT>>>(inB, tgB, w, out, out_size, N);
}

// round 17
// speedup vs baseline: 1.2140x; 1.2140x over previous
#include <cuda_runtime.h>
#include <cuda_bf16.h>

// MulticlassDice fused: nibble-packed histograms, R8 geometry (592x256) +
// R12 lean tail (early warp exit, single-warp shuffle epilogue).
// Inputs proven int32 at runtime (R5 ncu traffic = 16.8 MB = 2 x 8 MB).
// dice[n][c] = (2*inter + 1e-5) / (cnt_in + cnt_tg + 1e-5)
// Output: [total, dice[0..7]] (verified across R3..R16).
// BEST MEASURED: harness 8.70 us / ncu 9.248 us (R13). Locked in.

#define NCLS 8
#define PIX (512 * 512)
#define MAXN 8
#define GXB 74            // blocks per sample: 74*8 = 592 = 4/SM on 148 SMs
#define BT 256
#define NWARP (BT / 32)   // 8
#define NSLOT (3 * NCLS)  // 24
#define W32 (PIX / 4)     // 65536 int4 words per sample
#define CH32 ((W32 + GXB - 1) / GXB)  // 886

__device__ int g_cnt[MAXN][NSLOT];  // zero-init; last block re-zeros
__device__ unsigned int g_done;     // zero-init; last block resets

__device__ __forceinline__ void acc_px(int a, int b, unsigned& hin, unsigned& htg,
                                       unsigned& hxx) {
    unsigned sa = 1u << (4 * a);
    unsigned sb = 1u << (4 * b);
    hin += sa;
    htg += sb;
    if (a == b) hxx += sa;
}

__device__ __forceinline__ void acc4(const int4& va, const int4& vb, unsigned& hin,
                                     unsigned& htg, unsigned& hxx) {
    acc_px(va.x, vb.x, hin, htg, hxx);
    acc_px(va.y, vb.y, hin, htg, hxx);
    acc_px(va.z, vb.z, hin, htg, hxx);
    acc_px(va.w, vb.w, hin, htg, hxx);
}

// nibbles (cap 16) -> byte-packed (cap 256)
__device__ __forceinline__ void drain1(unsigned& h, unsigned& be, unsigned& bo) {
    be += h & 0x0F0F0F0Fu;
    bo += (h >> 4) & 0x0F0F0F0Fu;
    h = 0u;
}

__global__ __launch_bounds__(BT, 4) void k_dice_fused(const int* __restrict__ inB,
                                                      const int* __restrict__ tgB,
                                                      const float* __restrict__ w,
                                                      float* __restrict__ out,
                                                      int out_size, int N) {
    const int n = blockIdx.y;
    const int tid = threadIdx.x;
    const int lid = tid & 31;
    const int wid = tid >> 5;  // 0..7
    const unsigned FULL = 0xffffffffu;

    // ---- mainloop: loads first, all front-batched (8 LDG.128 per thread) ----
    const int4* a = (const int4*)inB + (size_t)n * W32;
    const int4* b = (const int4*)tgB + (size_t)n * W32;
    const int start = blockIdx.x * CH32;
    const int end = min(start + CH32, W32);
    const int i0 = start + tid, i1 = i0 + BT, i2 = i0 + 2 * BT, i3 = i0 + 3 * BT;
    const bool v0 = i0 < end, v1 = i1 < end, v2 = i2 < end, v3 = i3 < end;
    int4 a0, a1, a2, a3, b0, b1, b2, b3;
    if (v0) { a0 = a[i0]; b0 = b[i0]; }
    if (v1) { a1 = a[i1]; b1 = b[i1]; }
    if (v2) { a2 = a[i2]; b2 = b[i2]; }
    if (v3) { a3 = a[i3]; b3 = b[i3]; }

    unsigned hin = 0, htg = 0, hxx = 0;
    unsigned be_in = 0, bo_in = 0, be_tg = 0, bo_tg = 0, be_xx = 0, bo_xx = 0;

    // 16 px/thread max; drain at 8 px to respect nibble cap 15
    if (v0) acc4(a0, b0, hin, htg, hxx);
    if (v1) acc4(a1, b1, hin, htg, hxx);
    drain1(hin, be_in, bo_in);
    drain1(htg, be_tg, bo_tg);
    drain1(hxx, be_xx, bo_xx);
    if (v2) acc4(a2, b2, hin, htg, hxx);
    if (v3) acc4(a3, b3, hin, htg, hxx);
    drain1(hin, be_in, bo_in);
    drain1(htg, be_tg, bo_tg);
    drain1(hxx, be_xx, bo_xx);

    // ---- pack byte counters into 16-bit pairs, 12 REDUX per warp ----
    // per type: r0=(c0,c4), r1=(c2,c6), r2=(c1,c5), r3=(c3,c7)
    const unsigned M = 0x00FF00FFu;
    unsigned r[12];
    r[0] = be_in & M;  r[1] = (be_in >> 8) & M;
    r[2] = bo_in & M;  r[3] = (bo_in >> 8) & M;
    r[4] = be_tg & M;  r[5] = (be_tg >> 8) & M;
    r[6] = bo_tg & M;  r[7] = (bo_tg >> 8) & M;
    r[8] = be_xx & M;  r[9] = (be_xx >> 8) & M;
    r[10] = bo_xx & M; r[11] = (bo_xx >> 8) & M;
#pragma unroll
    for (int j = 0; j < 12; j++) r[j] = __reduce_add_sync(FULL, r[j]);

    __shared__ unsigned s_ph[NWARP][12];
    if (lid == 0) {
#pragma unroll
        for (int j = 0; j < 12; j++) s_ph[wid][j] = r[j];
    }
    __syncthreads();
    if (wid != 0) return;  // warps 1..7 done; warp 0 owns publish + epilogue

    // ---- warp 0: gather 24 slots across 8 warps, publish, release bump ----
    if (lid < NSLOT) {
        int t = lid / NCLS, c = lid % NCLS;
        int j = t * 4 + (c & 1) * 2 + ((c >> 1) & 1);
        int h = (c >> 2) * 16;
        int acc = 0;
#pragma unroll
        for (int ww = 0; ww < NWARP; ww++) acc += (int)((s_ph[ww][j] >> h) & 0xFFFFu);
        atomicAdd(&g_cnt[n][lid], acc);
    }
    __syncwarp(FULL);

    unsigned prev = 0;
    if (lid == 0) {
        unsigned int* gp = &g_done;
        asm volatile("atom.add.acq_rel.gpu.u32 %0, [%1], %2;"
                     : "=r"(prev)
                     : "l"(gp), "r"(1u)
                     : "memory");
    }
    prev = __shfl_sync(FULL, prev, 0);
    if (prev != (unsigned)(GXB * N - 1)) return;

    // ---- last block, warp 0 only: shuffle-based epilogue ----
    float wc = (lid < NCLS) ? __ldg(&w[lid]) : 0.0f;  // issue early

    // lane l: class c = l&7, covers samples n = l>>3 and n = (l>>3)+4
    const int c = lid & 7;
    const int h0 = lid >> 3;  // 0..3
    float m = 0.0f;
    if (h0 < N) {
        float inter = (float)g_cnt[h0][2 * NCLS + c];
        float sums = (float)(g_cnt[h0][0 * NCLS + c] + g_cnt[h0][1 * NCLS + c]);
        m += (2.0f * inter + 1e-5f) / (sums + 1e-5f);
    }
    if (h0 + 4 < N) {
        float inter = (float)g_cnt[h0 + 4][2 * NCLS + c];
        float sums = (float)(g_cnt[h0 + 4][0 * NCLS + c] + g_cnt[h0 + 4][1 * NCLS + c]);
        m += (2.0f * inter + 1e-5f) / (sums + 1e-5f);
    }
    m += __shfl_xor_sync(FULL, m, 8);
    m += __shfl_xor_sync(FULL, m, 16);
    const float mean = m / (float)N;  // lanes 0..7 hold mean dice for class lid

    // total = sum_c w[c]*mean_c : lanes 0..7 closed under xor {1,2,4}
    float t = (lid < NCLS) ? wc * mean : 0.0f;
    t += __shfl_xor_sync(FULL, t, 1);
    t += __shfl_xor_sync(FULL, t, 2);
    t += __shfl_xor_sync(FULL, t, 4);
    const float total = __shfl_sync(FULL, t, 0);

    if (out_size >= NCLS + 1) {
        if (lid == 0) out[0] = total;
        if (lid < NCLS) out[1 + lid] = mean;  // lane's c == lid for lid<8
        for (int i = NCLS + 1 + lid; i < out_size; i += 32) out[i] = 0.0f;
    } else if (out_size == NCLS) {
        if (lid < NCLS) out[lid] = mean;
    } else {
        if (lid == 0 && out_size > 0) out[0] = total;
        for (int i = 1 + lid; i < out_size; i += 32) out[i] = (i - 1 < NCLS) ? mean : 0.0f;
    }

    // ---- reset state for next graph replay (kernel boundary publishes) ----
    for (int i = lid; i < MAXN * NSLOT; i += 32) ((int*)g_cnt)[i] = 0;
    if (lid == 0) g_done = 0u;
}

extern "C" void kernel_launch(void* const* d_in, const int* in_sizes, int n_in,
                              void* d_out, int out_size) {
    const int* inB = (const int*)d_in[0];
    const int* tgB = (const int*)d_in[1];
    const float* w = (const float*)d_in[2];
    float* out = (float*)d_out;

    int N = in_sizes[0] / PIX;
    if (N < 1) N = 1;
    if (N > MAXN) N = MAXN;

    dim3 grid(GXB, N);
    k_dice_fused<<<grid, BT>>>(inB, tgB, w, out, out_size, N);
}